// round 16
// baseline (speedup 1.0000x reference)
#include <cuda_runtime.h>
#include <cuda_bf16.h>
#include <math.h>
#include <stdint.h>

// ---------------- problem constants ----------------
#define BB      8
#define NN_     1024
#define DIM_    512
#define HH      8
#define DD      64
#define INNER_  512
#define MTOK    3
#define CTX     2048            // 2*N
#define LK      2051            // 2N + M
#define LS      1027            // N + M
#define LKP     2080            // LK padded to mult of 32 (pads ZERO)
#define LSP     1056            // LS padded to mult of 32 (pads ZERO)
#define LCP     (LKP + LSP)     // 3136 = combined PS/GS row length
#define SCALE_  0.125f
#define SQRT_D  8.0f
#define SQRT_M  1.7320508075688772f
#define ZZ      (BB * HH)       // 64

typedef __nv_bfloat16 bf16;

// ---------------- scratch (device globals; no allocation allowed) ----------------
__device__ bf16 g_inp_h [BB * NN_ * DIM_],        g_inp_l [BB * NN_ * DIM_];
__device__ bf16 g_ctx_h [CTX * BB * DIM_],        g_ctx_l [CTX * BB * DIM_];
__device__ bf16 g_Wq_h  [INNER_ * DIM_],          g_Wq_l  [INNER_ * DIM_];
__device__ bf16 g_Wkv_h [2 * INNER_ * DIM_],      g_Wkv_l [2 * INNER_ * DIM_];
__device__ bf16 g_Wo_h  [DIM_ * INNER_],          g_Wo_l  [DIM_ * INNER_];
__device__ bf16 g_qlin_h[BB * NN_ * INNER_],      g_qlin_l[BB * NN_ * INNER_];
__device__ bf16 g_kctx_h[CTX * BB * INNER_],      g_kctx_l[CTX * BB * INNER_];
__device__ bf16 g_skv_h [BB * NN_ * 2 * INNER_],  g_skv_l [BB * NN_ * 2 * INNER_];
__device__ bf16 g_Q_h   [ZZ * NN_ * DD],          g_Q_l   [ZZ * NN_ * DD];
__device__ bf16 g_K_h   [ZZ * LKP * DD],          g_K_l   [ZZ * LKP * DD];
__device__ bf16 g_Sk_h  [ZZ * LSP * DD],          g_Sk_l  [ZZ * LSP * DD];
__device__ bf16 g_WfT_h [LKP * LSP],              g_WfT_l [LKP * LSP];
// combined probability buffer: row = [ P (LKP cols) | S2 (LSP cols) ]
__device__ bf16 g_PS_h  [(size_t)ZZ * NN_ * LCP], g_PS_l  [(size_t)ZZ * NN_ * LCP];
// combined value buffer per (z, d): row = [ Gt (LKP cols) | SvT (LSP cols) ]
__device__ bf16 g_GS_h  [ZZ * DD * LCP],          g_GS_l  [ZZ * DD * LCP];
__device__ bf16 g_outp_h[BB * NN_ * INNER_],      g_outp_l[BB * NN_ * INNER_];
// fp32 scratch
__device__ float g_PS32 [(size_t)ZZ * NN_ * LCP];  // raw logits (pads never read)
__device__ float g_cvec [ZZ * DD];

// ---------------- helpers ----------------
__device__ __forceinline__ void wsplit(float v, bf16* hi, bf16* lo, long idx)
{
    bf16 h = __float2bfloat16(v);
    hi[idx] = h;
    lo[idx] = __float2bfloat16(v - __bfloat162float(h));
}

__device__ __forceinline__ void ldsm4(uint32_t* r, uint32_t a)
{
    asm volatile("ldmatrix.sync.aligned.m8n8.x4.shared.b16 {%0,%1,%2,%3}, [%4];"
        : "=r"(r[0]), "=r"(r[1]), "=r"(r[2]), "=r"(r[3]) : "r"(a));
}
__device__ __forceinline__ void mma16816(float* d, const uint32_t* a, const uint32_t* b)
{
    asm volatile("mma.sync.aligned.m16n8k16.row.col.f32.bf16.bf16.f32 "
        "{%0,%1,%2,%3},{%4,%5,%6,%7},{%8,%9},{%0,%1,%2,%3};"
        : "+f"(d[0]), "+f"(d[1]), "+f"(d[2]), "+f"(d[3])
        : "r"(a[0]), "r"(a[1]), "r"(a[2]), "r"(a[3]), "r"(b[0]), "r"(b[1]));
}
__device__ __forceinline__ void cpa16(uint32_t dst, const bf16* src, int sz)
{
    asm volatile("cp.async.cg.shared.global [%0], [%1], 16, %2;"
        :: "r"(dst), "l"(src), "r"(sz) : "memory");
}
#define CP_COMMIT() asm volatile("cp.async.commit_group;" ::: "memory")
#define CP_WAIT1()  asm volatile("cp.async.wait_group 1;" ::: "memory")
#define CP_WAIT0()  asm volatile("cp.async.wait_group 0;" ::: "memory")

// ---------------- split-bf16 tensor-core NT GEMM (BK=32) ------------------------
// C = alpha * (A @ W^T) + bias + bias2_z + add, A ~= Ahi+Alo, W ~= Whi+Wlo.
// A: [M,K] rows (lda), W: [N,K] rows (ldw); lda/ldw mult of 8; K mult of 32.
// Outputs: fp32 C and/or split bf16 Chi/Clo (same ldc).
// merge != 0: split output head-merged: base = (bz>>3)*NN_*INNER_ + (bz&7)*DD.
// 3-stage cp.async pipeline; smem row: 32 hi | 32 lo | 8 pad (72 elems).
template<int BM, int BN>
__global__ __launch_bounds__(256)
void gemm_bf(const bf16* __restrict__ Ahi, const bf16* __restrict__ Alo, int lda, long sA,
             const bf16* __restrict__ Whi, const bf16* __restrict__ Wlo, int ldw, long sW,
             const float* __restrict__ bias,
             const float* __restrict__ bias2, long sB2,
             const float* __restrict__ addm, int ldadd, long sAdd,
             float* __restrict__ C, bf16* __restrict__ Chi, bf16* __restrict__ Clo,
             int ldc, long sC,
             int M, int N, int K, float alpha, int merge)
{
    constexpr int WARPS_M = (BM >= 128) ? 2 : 1;
    constexpr int WARPS_N = 8 / WARPS_M;
    constexpr int WM = BM / WARPS_M;       // 64
    constexpr int WN = BN / WARPS_N;       // 32 or 16
    constexpr int MI = WM / 16;            // 4
    constexpr int NJ = WN / 8;             // 4 or 2
    constexpr int NJ2 = NJ / 2;            // 2 or 1
    constexpr int R  = BM + BN;            // smem rows (A then B)
    constexpr int LDS = 72;                // elems/row: 32 hi | 32 lo | 8 pad
    constexpr int SS = R * LDS;            // elems per stage
    constexpr int NPASS = R / 64;          // loader passes (4 or 3)

    extern __shared__ __align__(16) bf16 sm[];   // 3 stages

    const long bz = blockIdx.z;
    const bf16* Ah_b = Ahi + bz * sA;
    const bf16* Al_b = Alo + bz * sA;
    const bf16* Wh_b = Whi + bz * sW;
    const bf16* Wl_b = Wlo + bz * sW;
    const float* Addb = addm ? (addm + bz * sAdd) : nullptr;
    const float* B2b  = bias2 ? (bias2 + bz * sB2) : nullptr;
    float* Cb = C ? (C + bz * sC) : nullptr;
    long coff = merge ? ((bz >> 3) * (long)NN_ * INNER_ + (bz & 7) * DD) : bz * sC;
    bf16* Chib = Chi ? (Chi + coff) : nullptr;
    bf16* Clob = Clo ? (Clo + coff) : nullptr;

    const int row0 = blockIdx.y * BM;
    const int col0 = blockIdx.x * BN;
    const int tid  = threadIdx.x;
    const int lane = tid & 31;
    const int warp = tid >> 5;
    const int wm   = warp % WARPS_M;
    const int wn   = warp / WARPS_M;

    // ---- coalesced loader: 4 threads per smem row; 2 chunks per 32-k slab
    // lc: 0,1 -> hi halves; 2,3 -> lo halves; within slab s, chunk at +s*16
    const int lrow = tid >> 2;             // 0..63
    const int lc   = tid & 3;
    const bf16* gsrc[NPASS];
    int gsz[NPASS];
    #pragma unroll
    for (int p = 0; p < NPASS; p++) {
        int r = p * 64 + lrow;
        bool isA = r < BM;
        int gr = isA ? (row0 + r) : (col0 + (r - BM));
        bool valid = isA ? (gr < M) : (gr < N);
        long ro = valid ? (long)gr * (isA ? lda : ldw) : 0;
        const bf16* h = isA ? Ah_b : Wh_b;
        const bf16* l = isA ? Al_b : Wl_b;
        gsrc[p] = ((lc < 2) ? h : l) + ro + (lc & 1) * 8;
        gsz[p] = valid ? 16 : 0;
    }
    const int cbase0 = (lc < 2 ? 0 : 32) + (lc & 1) * 8;   // smem chunk pos, slab 0

    const uint32_t sbase = (uint32_t)__cvta_generic_to_shared(&sm[0]);
    uint32_t aoff[MI], boff[NJ2];
    #pragma unroll
    for (int i = 0; i < MI; i++)
        aoff[i] = (uint32_t)(((wm * WM + i * 16 + (lane & 15)) * LDS + ((lane >> 4) * 8)) * 2);
    #pragma unroll
    for (int j2 = 0; j2 < NJ2; j2++)
        boff[j2] = (uint32_t)(((BM + wn * WN + j2 * 16 + (lane >> 4) * 8 + (lane & 7)) * LDS
                              + (((lane >> 3) & 1) * 8)) * 2);

    float acc[MI][NJ][4] = {};

    const int nk = K / 32;

#define ISSUE(t) do {                                                           \
        int _b = (t) % 3;                                                       \
        int _k0 = (t) * 32;                                                     \
        _Pragma("unroll")                                                       \
        for (int p = 0; p < NPASS; p++) {                                       \
            _Pragma("unroll")                                                   \
            for (int s = 0; s < 2; s++) {                                       \
                uint32_t dst = sbase + (uint32_t)((_b * SS + (p * 64 + lrow) * LDS \
                                                   + cbase0 + s * 16) * 2);     \
                cpa16(dst, gsrc[p] + _k0 + s * 16, gsz[p]);                     \
            }                                                                   \
        }                                                                       \
        CP_COMMIT();                                                            \
    } while (0)

    ISSUE(0);
    if (nk > 1) ISSUE(1);

    for (int t = 0; t < nk; t++) {
        if (t + 1 < nk) CP_WAIT1(); else CP_WAIT0();
        __syncthreads();

        const uint32_t bb = sbase + (uint32_t)((t % 3) * SS * 2);
        #pragma unroll
        for (int s = 0; s < 2; s++) {
            const uint32_t so = (uint32_t)(s * 32);
            uint32_t Ah[MI][4], Al[MI][4], Bh[NJ2][4], Bl[NJ2][4];
            #pragma unroll
            for (int i = 0; i < MI; i++) {
                ldsm4(Ah[i], bb + aoff[i] + so);
                ldsm4(Al[i], bb + aoff[i] + 64 + so);
            }
            #pragma unroll
            for (int j2 = 0; j2 < NJ2; j2++) {
                ldsm4(Bh[j2], bb + boff[j2] + so);
                ldsm4(Bl[j2], bb + boff[j2] + 64 + so);
            }
            #pragma unroll
            for (int i = 0; i < MI; i++)
                #pragma unroll
                for (int j = 0; j < NJ; j++) {
                    mma16816(acc[i][j], Ah[i], &Bh[j >> 1][(j & 1) * 2]);   // hi*hi
                    mma16816(acc[i][j], Ah[i], &Bl[j >> 1][(j & 1) * 2]);   // hi*lo
                    mma16816(acc[i][j], Al[i], &Bh[j >> 1][(j & 1) * 2]);   // lo*hi
                }
        }

        if (t + 2 < nk) ISSUE(t + 2);
    }
#undef ISSUE

    // ---- epilogue ----
    const int rbase = row0 + wm * WM + (lane >> 2);
    const int cbase = col0 + wn * WN + (lane & 3) * 2;
    #pragma unroll
    for (int i = 0; i < MI; i++)
        #pragma unroll
        for (int j = 0; j < NJ; j++)
            #pragma unroll
            for (int e = 0; e < 4; e++) {
                int r = rbase + i * 16 + (e >> 1) * 8;
                int c = cbase + j * 8 + (e & 1);
                if (r < M && c < N) {
                    float v = alpha * acc[i][j][e];
                    if (bias) v += bias[c];
                    if (B2b)  v += B2b[c];
                    if (Addb) v += Addb[(long)r * ldadd + c];
                    long o = (long)r * ldc + c;
                    if (Cb) Cb[o] = v;
                    if (Chib) {
                        bf16 h = __float2bfloat16(v);
                        Chib[o] = h;
                        Clob[o] = __float2bfloat16(v - __bfloat162float(h));
                    }
                }
            }
}

// ---------------- register-resident softmax -> split bf16 ----------------
// One block per row; operates on segment [col0, col0+cols) of a row with
// stride ld; writes normalized split bf16; pads [cols, padTo) ZEROED.
__global__ __launch_bounds__(256)
void softmax_split(const float* __restrict__ src,
                   bf16* __restrict__ dhi, bf16* __restrict__ dlo,
                   int col0, int cols, int padTo, int ld)
{
    const long row = blockIdx.x;
    const float* p = src + row * (long)ld + col0;
    bf16* ph = dhi + row * (long)ld + col0;
    bf16* pl = dlo + row * (long)ld + col0;
    const int tid = threadIdx.x;
    __shared__ float sh[256];

    float v[9];
    float mx = -3.0e38f;
    #pragma unroll
    for (int i = 0; i < 9; i++) {
        int c = tid + i * 256;
        if (c < cols) { v[i] = p[c]; mx = fmaxf(mx, v[i]); }
    }
    sh[tid] = mx; __syncthreads();
    for (int s = 128; s > 0; s >>= 1) {
        if (tid < s) sh[tid] = fmaxf(sh[tid], sh[tid + s]);
        __syncthreads();
    }
    mx = sh[0]; __syncthreads();

    float sum = 0.0f;
    #pragma unroll
    for (int i = 0; i < 9; i++) {
        int c = tid + i * 256;
        if (c < cols) { float e = __expf(v[i] - mx); v[i] = e; sum += e; }
    }
    sh[tid] = sum; __syncthreads();
    for (int s = 128; s > 0; s >>= 1) {
        if (tid < s) sh[tid] += sh[tid + s];
        __syncthreads();
    }
    float inv = 1.0f / sh[0];

    #pragma unroll
    for (int i = 0; i < 9; i++) {
        int c = tid + i * 256;
        if (c < cols) {
            float e = v[i] * inv;
            bf16 h = __float2bfloat16(e);
            ph[c] = h;
            pl[c] = __float2bfloat16(e - __bfloat162float(h));
        }
    }
    for (int c = cols + tid; c < padTo; c += 256) { ph[c] = __float2bfloat16(0.f); pl[c] = __float2bfloat16(0.f); }
}

// ---------------- fused input split + context pack (1 launch) ----------------
__global__ void split_all(const float* __restrict__ inp, const float* __restrict__ Wq,
                          const float* __restrict__ Wkv, const float* __restrict__ Wo,
                          const float* __restrict__ x, const float* __restrict__ y)
{
    long idx = (long)blockIdx.x * blockDim.x + threadIdx.x;
    const long n_inp = (long)BB * NN_ * DIM_;
    const long n_wq  = (long)INNER_ * DIM_;
    const long n_wkv = (long)2 * INNER_ * DIM_;
    const long n_wo  = (long)DIM_ * INNER_;
    const long n_ctx = (long)CTX * BB * DIM_;

    if (idx < n_inp) { wsplit(inp[idx], g_inp_h, g_inp_l, idx); return; }
    idx -= n_inp;
    if (idx < n_wq)  { wsplit(Wq[idx],  g_Wq_h,  g_Wq_l,  idx); return; }
    idx -= n_wq;
    if (idx < n_wkv) { wsplit(Wkv[idx], g_Wkv_h, g_Wkv_l, idx); return; }
    idx -= n_wkv;
    if (idx < n_wo)  { wsplit(Wo[idx],  g_Wo_h,  g_Wo_l,  idx); return; }
    idx -= n_wo;
    if (idx < n_ctx) {
        long b = idx / ((long)CTX * DIM_);
        long rem = idx - b * (long)CTX * DIM_;
        long j = rem / DIM_, c = rem - j * DIM_;
        float v = (j < NN_) ? x[(b * NN_ + j) * DIM_ + c]
                            : y[(b * NN_ + (j - NN_)) * DIM_ + c];
        wsplit(v, g_ctx_h, g_ctx_l, idx);
    }
}

// ---------------- pack kernels ----------------
__global__ void pack_Q_split()
{
    long idx = (long)blockIdx.x * blockDim.x + threadIdx.x;
    const long total = (long)ZZ * NN_ * DD;
    if (idx >= total) return;
    long z = idx / ((long)NN_ * DD);
    long rem = idx - z * (long)NN_ * DD;
    long n = rem / DD, d = rem - n * DD;
    long b = z >> 3, h = z & 7;
    long s = (b * NN_ + n) * INNER_ + h * DD + d;
    g_Q_h[idx] = g_qlin_h[s];
    g_Q_l[idx] = g_qlin_l[s];
}

__global__ void pack_K_split(const float* __restrict__ m_k)
{
    long idx = (long)blockIdx.x * blockDim.x + threadIdx.x;
    const long total = (long)ZZ * LKP * DD;
    if (idx >= total) return;
    long z = idx / ((long)LKP * DD);
    long rem = idx - z * (long)LKP * DD;
    long j = rem / DD, d = rem - j * DD;
    long b = z >> 3, h = z & 7;
    if (j < CTX) {
        long s = (b * CTX + j) * INNER_ + h * DD + d;
        g_K_h[idx] = g_kctx_h[s];
        g_K_l[idx] = g_kctx_l[s];
    } else if (j < LK) {
        wsplit(SQRT_D * m_k[h * (MTOK * DD) + (j - CTX) * DD + d], g_K_h, g_K_l, idx);
    } else {
        g_K_h[idx] = __float2bfloat16(0.f);
        g_K_l[idx] = __float2bfloat16(0.f);
    }
}

__global__ void pack_Sk_split(const float* __restrict__ Sm_k)
{
    long idx = (long)blockIdx.x * blockDim.x + threadIdx.x;
    const long total = (long)ZZ * LSP * DD;
    if (idx >= total) return;
    long z = idx / ((long)LSP * DD);
    long rem = idx - z * (long)LSP * DD;
    long j = rem / DD, d = rem - j * DD;
    long b = z >> 3, h = z & 7;
    if (j < NN_) {
        long s = (b * NN_ + j) * (2 * INNER_) + h * DD + d;
        g_Sk_h[idx] = g_skv_h[s];
        g_Sk_l[idx] = g_skv_l[s];
    } else if (j < LS) {
        wsplit(SQRT_D * Sm_k[h * (MTOK * DD) + (j - NN_) * DD + d], g_Sk_h, g_Sk_l, idx);
    } else {
        g_Sk_h[idx] = __float2bfloat16(0.f);
        g_Sk_l[idx] = __float2bfloat16(0.f);
    }
}

// SvT packed into the GS buffer at column offset LKP: GS[z][d][LKP + j]
__global__ void pack_SvT_split(const float* __restrict__ Sm_v)
{
    long idx = (long)blockIdx.x * blockDim.x + threadIdx.x;
    const long total = (long)ZZ * DD * LSP;
    if (idx >= total) return;
    long z = idx / ((long)DD * LSP);
    long rem = idx - z * (long)DD * LSP;
    long d = rem / LSP, j = rem - d * LSP;
    long b = z >> 3, h = z & 7;
    long o = (z * DD + d) * (long)LCP + LKP + j;
    if (j < NN_) {
        long s = (b * NN_ + j) * (2 * INNER_) + INNER_ + h * DD + d;
        g_GS_h[o] = g_skv_h[s];
        g_GS_l[o] = g_skv_l[s];
    } else if (j < LS) {
        wsplit(SQRT_M * Sm_v[h * (MTOK * DD) + (j - NN_) * DD + d], g_GS_h, g_GS_l, o);
    } else {
        g_GS_h[o] = __float2bfloat16(0.f);
        g_GS_l[o] = __float2bfloat16(0.f);
    }
}

// WfT[k, o] = Wf[o, k], split bf16, zero-padded to [LKP, LSP]
__global__ void transpose_WfT(const float* __restrict__ Wf)
{
    long idx = (long)blockIdx.x * blockDim.x + threadIdx.x;
    const long total = (long)LKP * LSP;
    if (idx >= total) return;
    long k = idx / LSP, o = idx - k * LSP;
    float v = (k < LK && o < LS) ? Wf[o * (long)LK + k] : 0.0f;
    wsplit(v, g_WfT_h, g_WfT_l, idx);
}

// cvec[z, d] = sum_o bf[o] * Sv[z, o, d]  (reads SvT inside GS; one warp per (z,d))
__global__ void calc_cvec(const float* __restrict__ bf)
{
    int w = (blockIdx.x * blockDim.x + threadIdx.x) >> 5;
    int lane = threadIdx.x & 31;
    if (w >= ZZ * DD) return;
    const bf16* sh_ = g_GS_h + (long)w * LCP + LKP;
    const bf16* sl_ = g_GS_l + (long)w * LCP + LKP;
    float s = 0.0f;
    for (int o = lane; o < LS; o += 32)
        s += bf[o] * (__bfloat162float(sh_[o]) + __bfloat162float(sl_[o]));
    #pragma unroll
    for (int sft = 16; sft > 0; sft >>= 1)
        s += __shfl_xor_sync(0xFFFFFFFF, s, sft);
    if (lane == 0) g_cvec[w] = s;
}

// ---------------- launch ----------------
static inline dim3 eltGrid(long n) { return dim3((unsigned)((n + 255) / 256)); }
static inline unsigned cdiv(int a, int b) { return (unsigned)((a + b - 1) / b); }

#define GETP(T, v, sym) T* v; cudaGetSymbolAddress((void**)&v, sym)

// dynamic smem sizes (3 stages x R x 72 elems x 2B)
#define SMEM_128_128 (3 * 256 * 72 * 2)
#define SMEM_64_128  (3 * 192 * 72 * 2)
#define SMEM_128_64  (3 * 192 * 72 * 2)

extern "C" void kernel_launch(void* const* d_in, const int* in_sizes, int n_in,
                              void* d_out, int out_size)
{
    const float* inp  = (const float*)d_in[0];
    const float* x    = (const float*)d_in[1];
    const float* y    = (const float*)d_in[2];
    const float* Wq   = (const float*)d_in[3];
    const float* bq   = (const float*)d_in[4];
    const float* Wkv  = (const float*)d_in[5];
    const float* bkv  = (const float*)d_in[6];
    const float* Wf   = (const float*)d_in[7];
    const float* bf   = (const float*)d_in[8];
    const float* Wo   = (const float*)d_in[9];
    const float* bo   = (const float*)d_in[10];
    const float* m_k  = (const float*)d_in[11];
    // d_in[12] = m_v : unused (cross-attention v never feeds the output)
    const float* Sm_k = (const float*)d_in[13];
    const float* Sm_v = (const float*)d_in[14];
    float* out = (float*)d_out;

    GETP(bf16, p_inp_h, g_inp_h);   GETP(bf16, p_inp_l, g_inp_l);
    GETP(bf16, p_ctx_h, g_ctx_h);   GETP(bf16, p_ctx_l, g_ctx_l);
    GETP(bf16, p_Wq_h,  g_Wq_h);    GETP(bf16, p_Wq_l,  g_Wq_l);
    GETP(bf16, p_Wkv_h, g_Wkv_h);   GETP(bf16, p_Wkv_l, g_Wkv_l);
    GETP(bf16, p_Wo_h,  g_Wo_h);    GETP(bf16, p_Wo_l,  g_Wo_l);
    GETP(bf16, p_qlin_h,g_qlin_h);  GETP(bf16, p_qlin_l,g_qlin_l);
    GETP(bf16, p_kctx_h,g_kctx_h);  GETP(bf16, p_kctx_l,g_kctx_l);
    GETP(bf16, p_skv_h, g_skv_h);   GETP(bf16, p_skv_l, g_skv_l);
    GETP(bf16, p_Q_h,   g_Q_h);     GETP(bf16, p_Q_l,   g_Q_l);
    GETP(bf16, p_K_h,   g_K_h);     GETP(bf16, p_K_l,   g_K_l);
    GETP(bf16, p_Sk_h,  g_Sk_h);    GETP(bf16, p_Sk_l,  g_Sk_l);
    GETP(bf16, p_WfT_h, g_WfT_h);   GETP(bf16, p_WfT_l, g_WfT_l);
    GETP(bf16, p_PS_h,  g_PS_h);    GETP(bf16, p_PS_l,  g_PS_l);
    GETP(bf16, p_GS_h,  g_GS_h);    GETP(bf16, p_GS_l,  g_GS_l);
    GETP(bf16, p_outp_h,g_outp_h);  GETP(bf16, p_outp_l,g_outp_l);
    GETP(float, p_PS32, g_PS32);
    GETP(float, p_cvec, g_cvec);

    cudaFuncSetAttribute((const void*)gemm_bf<128,128>,
                         cudaFuncAttributeMaxDynamicSharedMemorySize, SMEM_128_128);
    cudaFuncSetAttribute((const void*)gemm_bf<64,128>,
                         cudaFuncAttributeMaxDynamicSharedMemorySize, SMEM_64_128);
    cudaFuncSetAttribute((const void*)gemm_bf<128,64>,
                         cudaFuncAttributeMaxDynamicSharedMemorySize, SMEM_128_64);

    // 1. fused input splits + context pack (ONE launch)
    const long n_split = (long)BB * NN_ * DIM_ + (long)INNER_ * DIM_
                       + (long)2 * INNER_ * DIM_ + (long)DIM_ * INNER_
                       + (long)CTX * BB * DIM_;
    split_all<<<eltGrid(n_split), 256>>>(inp, Wq, Wkv, Wo, x, y);

    // 2. q_lin = inp @ Wq^T + bq   [8192, 512] K=512 -> split bf16
    gemm_bf<128,128><<<dim3(cdiv(INNER_,128), cdiv(BB*NN_,128), 1), 256, SMEM_128_128>>>(
        p_inp_h, p_inp_l, DIM_, 0, p_Wq_h, p_Wq_l, DIM_, 0,
        bq, nullptr, 0, nullptr, 0, 0,
        nullptr, p_qlin_h, p_qlin_l, INNER_, 0, BB*NN_, INNER_, DIM_, 1.0f, 0);

    // 3. k_ctx = context @ Wkv[0:512]^T + bkv[0:512]   [16384, 512] (v half dead)
    gemm_bf<128,128><<<dim3(cdiv(INNER_,128), cdiv(BB*CTX,128), 1), 256, SMEM_128_128>>>(
        p_ctx_h, p_ctx_l, DIM_, 0, p_Wkv_h, p_Wkv_l, DIM_, 0,
        bkv, nullptr, 0, nullptr, 0, 0,
        nullptr, p_kctx_h, p_kctx_l, INNER_, 0, BB*CTX, INNER_, DIM_, 1.0f, 0);

    // 4. skv = inp @ Wkv^T + bkv   [8192, 1024]
    gemm_bf<128,128><<<dim3(cdiv(2*INNER_,128), cdiv(BB*NN_,128), 1), 256, SMEM_128_128>>>(
        p_inp_h, p_inp_l, DIM_, 0, p_Wkv_h, p_Wkv_l, DIM_, 0,
        bkv, nullptr, 0, nullptr, 0, 0,
        nullptr, p_skv_h, p_skv_l, 2*INNER_, 0, BB*NN_, 2*INNER_, DIM_, 1.0f, 0);

    // 5. packs (+ memory tokens, + zero pads), WfT, cvec
    pack_Q_split  <<<eltGrid((long)ZZ * NN_ * DD), 256>>>();
    pack_K_split  <<<eltGrid((long)ZZ * LKP * DD), 256>>>(m_k);
    pack_Sk_split <<<eltGrid((long)ZZ * LSP * DD), 256>>>(Sm_k);
    pack_SvT_split<<<eltGrid((long)ZZ * DD * LSP), 256>>>(Sm_v);
    transpose_WfT <<<eltGrid((long)LKP * LSP), 256>>>(Wf);
    calc_cvec     <<<cdiv(ZZ * DD * 32, 256), 256>>>(bf);

    // 6. cross scores -> PS32 cols [0, LK): SCALE * Q @ K^T   K=64
    gemm_bf<128,128><<<dim3(cdiv(LK,128), cdiv(NN_,128), ZZ), 256, SMEM_128_128>>>(
        p_Q_h, p_Q_l, DD, (long)NN_*DD, p_K_h, p_K_l, DD, (long)LKP*DD,
        nullptr, nullptr, 0, nullptr, 0, 0,
        p_PS32, nullptr, nullptr, LCP, (long)NN_*LCP, NN_, LK, DD, SCALE_, 0);

    //    self scores -> PS32 cols [LKP, LKP+LS): SCALE * Q @ Sk^T   K=64
    gemm_bf<128,128><<<dim3(cdiv(LS,128), cdiv(NN_,128), ZZ), 256, SMEM_128_128>>>(
        p_Q_h, p_Q_l, DD, (long)NN_*DD, p_Sk_h, p_Sk_l, DD, (long)LSP*DD,
        nullptr, nullptr, 0, nullptr, 0, 0,
        p_PS32 + LKP, nullptr, nullptr, LCP, (long)NN_*LCP, NN_, LS, DD, SCALE_, 0);

    // 7. per-segment softmax -> normalized split bf16 into PS (pads zeroed)
    softmax_split<<<ZZ * NN_, 256>>>(p_PS32, p_PS_h, p_PS_l, 0,   LK, LKP, LCP);
    softmax_split<<<ZZ * NN_, 256>>>(p_PS32, p_PS_h, p_PS_l, LKP, LS, LSP, LCP);

    // 8a. Gt[z][d,k] = sum_o Sv[o,d] Wf[o,k] -> GS cols [0, LKP)
    //     A = SvT portion of GS (cols LKP..), M=64, N=LKP, K=LSP=1056
    gemm_bf<64,128><<<dim3(cdiv(LKP,128), 1, ZZ), 256, SMEM_64_128>>>(
        p_GS_h + LKP, p_GS_l + LKP, LCP, (long)DD*LCP, p_WfT_h, p_WfT_l, LSP, 0,
        nullptr, nullptr, 0, nullptr, 0, 0,
        nullptr, p_GS_h, p_GS_l, LCP, (long)DD*LCP, DD, LKP, LSP, 1.0f, 0);

    // 8b. outp = PS @ GS^T + cvec  (= P@Gt^T + S2@Sv + bf·Sv) -> split bf16,
    //     HEAD-MERGED  [64 x 1024 x 64, K=3136]
    gemm_bf<128,64><<<dim3(1, cdiv(NN_,128), ZZ), 256, SMEM_128_64>>>(
        p_PS_h, p_PS_l, LCP, (long)NN_*LCP, p_GS_h, p_GS_l, LCP, (long)DD*LCP,
        nullptr, p_cvec, DD, nullptr, 0, 0,
        nullptr, p_outp_h, p_outp_l, INNER_, 0, NN_, DD, LCP, 1.0f, 1);

    // 9. final = outp @ Wo^T + bo   [8192, 512] K=512 -> fp32 d_out
    gemm_bf<128,128><<<dim3(cdiv(DIM_,128), cdiv(BB*NN_,128), 1), 256, SMEM_128_128>>>(
        p_outp_h, p_outp_l, INNER_, 0, p_Wo_h, p_Wo_l, INNER_, 0,
        bo, nullptr, 0, nullptr, 0, 0,
        out, nullptr, nullptr, DIM_, 0, BB*NN_, DIM_, INNER_, 1.0f, 0);
}

// round 17
// speedup vs baseline: 1.1520x; 1.1520x over previous
#include <cuda_runtime.h>
#include <cuda_bf16.h>
#include <math.h>
#include <stdint.h>

// ---------------- problem constants ----------------
#define BB      8
#define NN_     1024
#define DIM_    512
#define HH      8
#define DD      64
#define INNER_  512
#define MTOK    3
#define CTX     2048            // 2*N
#define LK      2051            // 2N + M
#define LS      1027            // N + M
#define LKP     2064            // LK padded to mult of 16 (pads ZERO)
#define LSP     1040            // LS padded to mult of 16 (pads ZERO)
#define SCALE_  0.125f
#define SQRT_D  8.0f
#define SQRT_M  1.7320508075688772f
#define ZZ      (BB * HH)       // 64

typedef __nv_bfloat16 bf16;

// ---------------- scratch (device globals; no allocation allowed) ----------------
__device__ bf16 g_inp_h [BB * NN_ * DIM_],        g_inp_l [BB * NN_ * DIM_];
__device__ bf16 g_ctx_h [CTX * BB * DIM_],        g_ctx_l [CTX * BB * DIM_];
__device__ bf16 g_Wq_h  [INNER_ * DIM_],          g_Wq_l  [INNER_ * DIM_];
__device__ bf16 g_Wkv_h [2 * INNER_ * DIM_],      g_Wkv_l [2 * INNER_ * DIM_];
__device__ bf16 g_Wo_h  [DIM_ * INNER_],          g_Wo_l  [DIM_ * INNER_];
__device__ bf16 g_qlin_h[BB * NN_ * INNER_],      g_qlin_l[BB * NN_ * INNER_];
__device__ bf16 g_kctx_h[CTX * BB * INNER_],      g_kctx_l[CTX * BB * INNER_];
__device__ bf16 g_skv_h [BB * NN_ * 2 * INNER_],  g_skv_l [BB * NN_ * 2 * INNER_];
__device__ bf16 g_Q_h   [ZZ * NN_ * DD],          g_Q_l   [ZZ * NN_ * DD];
__device__ bf16 g_K_h   [ZZ * LKP * DD],          g_K_l   [ZZ * LKP * DD];
__device__ bf16 g_Sk_h  [ZZ * LSP * DD],          g_Sk_l  [ZZ * LSP * DD];
__device__ bf16 g_SvT_h [ZZ * DD * LSP],          g_SvT_l [ZZ * DD * LSP];
__device__ bf16 g_WfT_h [LKP * LSP],              g_WfT_l [LKP * LSP];
__device__ bf16 g_Ph    [(size_t)ZZ * NN_ * LKP], g_Pl    [(size_t)ZZ * NN_ * LKP];  // exp, UNnormalized
__device__ bf16 g_S2h   [(size_t)ZZ * NN_ * LSP], g_S2l   [(size_t)ZZ * NN_ * LSP];
__device__ bf16 g_Gt_h  [ZZ * DD * LKP],          g_Gt_l  [ZZ * DD * LKP];
__device__ bf16 g_outp_h[BB * NN_ * INNER_],      g_outp_l[BB * NN_ * INNER_];
// fp32 scratch
__device__ float g_rsumP[ZZ * NN_];                // row sums of exp (cross)
__device__ float g_rsumS[ZZ * NN_];                // row sums of exp (self)
__device__ float g_cvec [ZZ * DD];
__device__ float g_obh  [ZZ * NN_ * DD];

// ---------------- helpers ----------------
__device__ __forceinline__ void wsplit(float v, bf16* hi, bf16* lo, long idx)
{
    bf16 h = __float2bfloat16(v);
    hi[idx] = h;
    lo[idx] = __float2bfloat16(v - __bfloat162float(h));
}
__device__ __forceinline__ uint32_t pack2(float a, float b)
{
    __nv_bfloat162 p = __floats2bfloat162_rn(a, b);   // (a -> x/low, b -> y/high)
    return *reinterpret_cast<uint32_t*>(&p);
}

__device__ __forceinline__ void ldsm4(uint32_t* r, uint32_t a)
{
    asm volatile("ldmatrix.sync.aligned.m8n8.x4.shared.b16 {%0,%1,%2,%3}, [%4];"
        : "=r"(r[0]), "=r"(r[1]), "=r"(r[2]), "=r"(r[3]) : "r"(a));
}
__device__ __forceinline__ void mma16816(float* d, const uint32_t* a, const uint32_t* b)
{
    asm volatile("mma.sync.aligned.m16n8k16.row.col.f32.bf16.bf16.f32 "
        "{%0,%1,%2,%3},{%4,%5,%6,%7},{%8,%9},{%0,%1,%2,%3};"
        : "+f"(d[0]), "+f"(d[1]), "+f"(d[2]), "+f"(d[3])
        : "r"(a[0]), "r"(a[1]), "r"(a[2]), "r"(a[3]), "r"(b[0]), "r"(b[1]));
}
__device__ __forceinline__ void cpa16(uint32_t dst, const bf16* src, int sz)
{
    asm volatile("cp.async.cg.shared.global [%0], [%1], 16, %2;"
        :: "r"(dst), "l"(src), "r"(sz) : "memory");
}
#define CP_COMMIT() asm volatile("cp.async.commit_group;" ::: "memory")
#define CP_WAIT1()  asm volatile("cp.async.wait_group 1;" ::: "memory")

// ---------------- split-bf16 tensor-core NT GEMM --------------------------------
// C = alpha * (A @ W^T) + bias + bias2_z + add, A ~= Ahi+Alo, W ~= Whi+Wlo.
// A: [M,K] rows (lda), W: [N,K] rows (ldw); lda/ldw mult of 8; K mult of 16.
// Epilogue modes:
//  * rsum_out != nullptr ("exp mode"): Chi/Clo <- split bf16 of exp(alpha*acc);
//    cols [N, ldpadN) zeroed; row sums of exp atomically added to
//    rsum_out[bz*sRs + r] (pre-zeroed). Stores are STAGED through smem and
//    written as coalesced 16B chunks.
//  * rowsum_in != nullptr: result scaled by 1/rowsum_in[bz*sRsi + r] before
//    bias2/add (softmax normalization deferred to output).
//  * merge != 0: split output head-merged: base = (bz>>3)*NN_*INNER_ + (bz&7)*DD.
// 3-stage cp.async pipeline; coalesced loader; ldsm4-paired B fragments.
// In-place C == addm safe.
template<int BM, int BN>
__global__ __launch_bounds__(256)
void gemm_bf(const bf16* __restrict__ Ahi, const bf16* __restrict__ Alo, int lda, long sA,
             const bf16* __restrict__ Whi, const bf16* __restrict__ Wlo, int ldw, long sW,
             const float* __restrict__ bias,
             const float* __restrict__ bias2, long sB2,
             const float* __restrict__ addm, int ldadd, long sAdd,
             float* __restrict__ C, bf16* __restrict__ Chi, bf16* __restrict__ Clo,
             int ldc, long sC,
             int M, int N, int K, float alpha,
             float* __restrict__ rsum_out, long sRs, int ldpadN,
             const float* __restrict__ rowsum_in, long sRsi,
             int merge)
{
    constexpr int WARPS_M = (BM >= 128) ? 2 : 1;
    constexpr int WARPS_N = 8 / WARPS_M;
    constexpr int WM = BM / WARPS_M;       // 64
    constexpr int WN = BN / WARPS_N;       // 32 or 16
    constexpr int MI = WM / 16;            // 4
    constexpr int NJ = WN / 8;             // 4 or 2
    constexpr int NJ2 = NJ / 2;            // 2 or 1
    constexpr int R  = BM + BN;            // smem rows (A then B)
    constexpr int LDS = 40;                // elems/row: 16 hi | 16 lo | 8 pad
    constexpr int SS = R * LDS;            // elems per stage
    constexpr int NPASS = R / 64;          // loader passes (4 or 3)
    constexpr int EPLD = BN + 8;           // staging row elems (pad)

    extern __shared__ __align__(16) bf16 sm[];   // 3 stages / reused for staging

    const long bz = blockIdx.z;
    const bf16* Ah_b = Ahi + bz * sA;
    const bf16* Al_b = Alo + bz * sA;
    const bf16* Wh_b = Whi + bz * sW;
    const bf16* Wl_b = Wlo + bz * sW;
    const float* Addb = addm ? (addm + bz * sAdd) : nullptr;
    const float* B2b  = bias2 ? (bias2 + bz * sB2) : nullptr;
    float* Cb = C ? (C + bz * sC) : nullptr;
    long coff = merge ? ((bz >> 3) * (long)NN_ * INNER_ + (bz & 7) * DD) : bz * sC;
    bf16* Chib = Chi ? (Chi + coff) : nullptr;
    bf16* Clob = Clo ? (Clo + coff) : nullptr;

    const int row0 = blockIdx.y * BM;
    const int col0 = blockIdx.x * BN;
    const int tid  = threadIdx.x;
    const int lane = tid & 31;
    const int warp = tid >> 5;
    const int wm   = warp % WARPS_M;
    const int wn   = warp / WARPS_M;

    // ---- coalesced loader: 4 threads per smem row
    const int lrow = tid >> 2;             // 0..63
    const int lc   = tid & 3;
    const bf16* gsrc[NPASS];
    int gsz[NPASS];
    #pragma unroll
    for (int p = 0; p < NPASS; p++) {
        int r = p * 64 + lrow;
        bool isA = r < BM;
        int gr = isA ? (row0 + r) : (col0 + (r - BM));
        bool valid = isA ? (gr < M) : (gr < N);
        long ro = valid ? (long)gr * (isA ? lda : ldw) : 0;
        const bf16* h = isA ? Ah_b : Wh_b;
        const bf16* l = isA ? Al_b : Wl_b;
        gsrc[p] = ((lc < 2) ? h : l) + ro + (lc & 1) * 8;
        gsz[p] = valid ? 16 : 0;
    }

    const uint32_t sbase = (uint32_t)__cvta_generic_to_shared(&sm[0]);
    uint32_t aoff[MI], boff[NJ2];
    #pragma unroll
    for (int i = 0; i < MI; i++)
        aoff[i] = (uint32_t)(((wm * WM + i * 16 + (lane & 15)) * LDS + ((lane >> 4) * 8)) * 2);
    #pragma unroll
    for (int j2 = 0; j2 < NJ2; j2++)
        boff[j2] = (uint32_t)(((BM + wn * WN + j2 * 16 + (lane >> 4) * 8 + (lane & 7)) * LDS
                              + (((lane >> 3) & 1) * 8)) * 2);

    float acc[MI][NJ][4] = {};

    const int nk = K / 16;

#define ISSUE(t) do {                                                           \
        int _b = (t) % 3;                                                       \
        int _k0 = (t) * 16;                                                     \
        _Pragma("unroll")                                                       \
        for (int p = 0; p < NPASS; p++) {                                       \
            uint32_t dst = sbase + (uint32_t)((_b * SS + (p * 64 + lrow) * LDS + lc * 8) * 2); \
            cpa16(dst, gsrc[p] + _k0, gsz[p]);                                  \
        }                                                                       \
        CP_COMMIT();                                                            \
    } while (0)

    ISSUE(0);
    ISSUE(1);

    for (int t = 0; t < nk; t++) {
        CP_WAIT1();
        __syncthreads();

        const uint32_t bb = sbase + (uint32_t)((t % 3) * SS * 2);
        uint32_t Ah[MI][4], Al[MI][4], Bh[NJ2][4], Bl[NJ2][4];
        #pragma unroll
        for (int i = 0; i < MI; i++) {
            ldsm4(Ah[i], bb + aoff[i]);
            ldsm4(Al[i], bb + aoff[i] + 32);
        }
        #pragma unroll
        for (int j2 = 0; j2 < NJ2; j2++) {
            ldsm4(Bh[j2], bb + boff[j2]);
            ldsm4(Bl[j2], bb + boff[j2] + 32);
        }
        #pragma unroll
        for (int i = 0; i < MI; i++)
            #pragma unroll
            for (int j = 0; j < NJ; j++) {
                mma16816(acc[i][j], Ah[i], &Bh[j >> 1][(j & 1) * 2]);   // hi*hi
                mma16816(acc[i][j], Ah[i], &Bl[j >> 1][(j & 1) * 2]);   // hi*lo
                mma16816(acc[i][j], Al[i], &Bh[j >> 1][(j & 1) * 2]);   // lo*hi
            }

        if (t + 2 < nk) ISSUE(t + 2);
        else            CP_COMMIT();
    }
#undef ISSUE

    const int rbase = row0 + wm * WM + (lane >> 2);
    const int cbase = col0 + wn * WN + (lane & 3) * 2;

    // ================= exp mode: staged coalesced split-exp writes =================
    if (rsum_out) {
        float* rsb = rsum_out + bz * sRs;
        bf16* plane_h = sm;                       // [64][EPLD]
        bf16* plane_l = sm + 64 * EPLD;
        const int cw = (ldpadN - col0 < BN) ? (ldpadN - col0) : BN;

        #pragma unroll
        for (int h = 0; h < WARPS_M; h++) {
            __syncthreads();      // smem free / previous half stored
            if (wm == h) {
                #pragma unroll
                for (int i = 0; i < MI; i++) {
                    float rs0 = 0.f, rs1 = 0.f;
                    const int lr = i * 16 + (lane >> 2);
                    #pragma unroll
                    for (int j = 0; j < NJ; j++) {
                        const int c = cbase + j * 8;   // first of the 2 cols
                        float e0 = (c     < N) ? __expf(alpha * acc[i][j][0]) : 0.f;
                        float e1 = (c + 1 < N) ? __expf(alpha * acc[i][j][1]) : 0.f;
                        float e2 = (c     < N) ? __expf(alpha * acc[i][j][2]) : 0.f;
                        float e3 = (c + 1 < N) ? __expf(alpha * acc[i][j][3]) : 0.f;
                        rs0 += e0 + e1;
                        rs1 += e2 + e3;
                        const int lcw = wn * WN + j * 8 + (lane & 3) * 2;
                        // hi parts
                        bf16 h0 = __float2bfloat16(e0), h1 = __float2bfloat16(e1);
                        bf16 h2 = __float2bfloat16(e2), h3 = __float2bfloat16(e3);
                        *reinterpret_cast<uint32_t*>(&plane_h[lr * EPLD + lcw]) =
                            (uint32_t)*reinterpret_cast<uint16_t*>(&h0) |
                            ((uint32_t)*reinterpret_cast<uint16_t*>(&h1) << 16);
                        *reinterpret_cast<uint32_t*>(&plane_h[(lr + 8) * EPLD + lcw]) =
                            (uint32_t)*reinterpret_cast<uint16_t*>(&h2) |
                            ((uint32_t)*reinterpret_cast<uint16_t*>(&h3) << 16);
                        // lo parts
                        bf16 l0 = __float2bfloat16(e0 - __bfloat162float(h0));
                        bf16 l1 = __float2bfloat16(e1 - __bfloat162float(h1));
                        bf16 l2 = __float2bfloat16(e2 - __bfloat162float(h2));
                        bf16 l3 = __float2bfloat16(e3 - __bfloat162float(h3));
                        *reinterpret_cast<uint32_t*>(&plane_l[lr * EPLD + lcw]) =
                            (uint32_t)*reinterpret_cast<uint16_t*>(&l0) |
                            ((uint32_t)*reinterpret_cast<uint16_t*>(&l1) << 16);
                        *reinterpret_cast<uint32_t*>(&plane_l[(lr + 8) * EPLD + lcw]) =
                            (uint32_t)*reinterpret_cast<uint16_t*>(&l2) |
                            ((uint32_t)*reinterpret_cast<uint16_t*>(&l3) << 16);
                    }
                    rs0 += __shfl_xor_sync(0xFFFFFFFF, rs0, 1);
                    rs0 += __shfl_xor_sync(0xFFFFFFFF, rs0, 2);
                    rs1 += __shfl_xor_sync(0xFFFFFFFF, rs1, 1);
                    rs1 += __shfl_xor_sync(0xFFFFFFFF, rs1, 2);
                    if ((lane & 3) == 0) {
                        int r = row0 + h * 64 + lr;
                        if (r < M)     atomicAdd(&rsb[r], rs0);
                        if (r + 8 < M) atomicAdd(&rsb[r + 8], rs1);
                    }
                }
            }
            __syncthreads();
            // coalesced store-out: 64 rows x cw cols (hi and lo)
            const int rowg0 = row0 + h * 64;
            #pragma unroll
            for (int pass = 0; pass < 4; pass++) {
                int rr = pass * 16 + (tid >> 4);
                int ch = (tid & 15) * 8;
                int rg = rowg0 + rr;
                if (ch < cw && rg < M) {
                    long o = (long)rg * ldc + col0 + ch;
                    *reinterpret_cast<uint4*>(Chib + o) =
                        *reinterpret_cast<const uint4*>(&plane_h[rr * EPLD + ch]);
                    *reinterpret_cast<uint4*>(Clob + o) =
                        *reinterpret_cast<const uint4*>(&plane_l[rr * EPLD + ch]);
                }
            }
        }
        return;
    }

    // ================= normal epilogue =================
    float rw[MI][2];
    if (rowsum_in) {
        const float* rsb = rowsum_in + bz * sRsi;
        #pragma unroll
        for (int i = 0; i < MI; i++)
            #pragma unroll
            for (int h2 = 0; h2 < 2; h2++) {
                int r = rbase + i * 16 + h2 * 8;
                rw[i][h2] = (r < M) ? 1.0f / rsb[r] : 0.0f;
            }
    }
    #pragma unroll
    for (int i = 0; i < MI; i++)
        #pragma unroll
        for (int j = 0; j < NJ; j++)
            #pragma unroll
            for (int e = 0; e < 4; e++) {
                int r = rbase + i * 16 + (e >> 1) * 8;
                int c = cbase + j * 8 + (e & 1);
                if (r < M && c < N) {
                    float v = alpha * acc[i][j][e];
                    if (rowsum_in) v *= rw[i][e >> 1];
                    if (bias) v += bias[c];
                    if (B2b)  v += B2b[c];
                    if (Addb) v += Addb[(long)r * ldadd + c];
                    long o = (long)r * ldc + c;
                    if (Cb) Cb[o] = v;
                    if (Chib) {
                        bf16 h = __float2bfloat16(v);
                        Chib[o] = h;
                        Clob[o] = __float2bfloat16(v - __bfloat162float(h));
                    }
                }
            }
}

// ---------------- fused input split + context pack (1 launch) ----------------
__global__ void split_all(const float* __restrict__ inp, const float* __restrict__ Wq,
                          const float* __restrict__ Wkv, const float* __restrict__ Wo,
                          const float* __restrict__ x, const float* __restrict__ y)
{
    long idx = (long)blockIdx.x * blockDim.x + threadIdx.x;
    const long n_inp = (long)BB * NN_ * DIM_;
    const long n_wq  = (long)INNER_ * DIM_;
    const long n_wkv = (long)2 * INNER_ * DIM_;
    const long n_wo  = (long)DIM_ * INNER_;
    const long n_ctx = (long)CTX * BB * DIM_;

    if (idx < n_inp) { wsplit(inp[idx], g_inp_h, g_inp_l, idx); return; }
    idx -= n_inp;
    if (idx < n_wq)  { wsplit(Wq[idx],  g_Wq_h,  g_Wq_l,  idx); return; }
    idx -= n_wq;
    if (idx < n_wkv) { wsplit(Wkv[idx], g_Wkv_h, g_Wkv_l, idx); return; }
    idx -= n_wkv;
    if (idx < n_wo)  { wsplit(Wo[idx],  g_Wo_h,  g_Wo_l,  idx); return; }
    idx -= n_wo;
    if (idx < n_ctx) {
        long b = idx / ((long)CTX * DIM_);
        long rem = idx - b * (long)CTX * DIM_;
        long j = rem / DIM_, c = rem - j * DIM_;
        float v = (j < NN_) ? x[(b * NN_ + j) * DIM_ + c]
                            : y[(b * NN_ + (j - NN_)) * DIM_ + c];
        wsplit(v, g_ctx_h, g_ctx_l, idx);
    }
}

// ---------------- pack kernels ----------------
__global__ void pack_Q_split()
{
    long idx = (long)blockIdx.x * blockDim.x + threadIdx.x;
    const long total = (long)ZZ * NN_ * DD;
    if (idx >= total) return;
    long z = idx / ((long)NN_ * DD);
    long rem = idx - z * (long)NN_ * DD;
    long n = rem / DD, d = rem - n * DD;
    long b = z >> 3, h = z & 7;
    long s = (b * NN_ + n) * INNER_ + h * DD + d;
    g_Q_h[idx] = g_qlin_h[s];
    g_Q_l[idx] = g_qlin_l[s];
}

__global__ void pack_K_split(const float* __restrict__ m_k)
{
    long idx = (long)blockIdx.x * blockDim.x + threadIdx.x;
    const long total = (long)ZZ * LKP * DD;
    if (idx >= total) return;
    long z = idx / ((long)LKP * DD);
    long rem = idx - z * (long)LKP * DD;
    long j = rem / DD, d = rem - j * DD;
    long b = z >> 3, h = z & 7;
    if (j < CTX) {
        long s = (b * CTX + j) * INNER_ + h * DD + d;
        g_K_h[idx] = g_kctx_h[s];
        g_K_l[idx] = g_kctx_l[s];
    } else if (j < LK) {
        wsplit(SQRT_D * m_k[h * (MTOK * DD) + (j - CTX) * DD + d], g_K_h, g_K_l, idx);
    } else {
        g_K_h[idx] = __float2bfloat16(0.f);
        g_K_l[idx] = __float2bfloat16(0.f);
    }
}

__global__ void pack_Sk_split(const float* __restrict__ Sm_k)
{
    long idx = (long)blockIdx.x * blockDim.x + threadIdx.x;
    const long total = (long)ZZ * LSP * DD;
    if (idx >= total) return;
    long z = idx / ((long)LSP * DD);
    long rem = idx - z * (long)LSP * DD;
    long j = rem / DD, d = rem - j * DD;
    long b = z >> 3, h = z & 7;
    if (j < NN_) {
        long s = (b * NN_ + j) * (2 * INNER_) + h * DD + d;
        g_Sk_h[idx] = g_skv_h[s];
        g_Sk_l[idx] = g_skv_l[s];
    } else if (j < LS) {
        wsplit(SQRT_D * Sm_k[h * (MTOK * DD) + (j - NN_) * DD + d], g_Sk_h, g_Sk_l, idx);
    } else {
        g_Sk_h[idx] = __float2bfloat16(0.f);
        g_Sk_l[idx] = __float2bfloat16(0.f);
    }
}

__global__ void pack_SvT_split(const float* __restrict__ Sm_v)
{
    long idx = (long)blockIdx.x * blockDim.x + threadIdx.x;
    const long total = (long)ZZ * DD * LSP;
    if (idx >= total) return;
    long z = idx / ((long)DD * LSP);
    long rem = idx - z * (long)DD * LSP;
    long d = rem / LSP, j = rem - d * LSP;
    long b = z >> 3, h = z & 7;
    if (j < NN_) {
        long s = (b * NN_ + j) * (2 * INNER_) + INNER_ + h * DD + d;
        g_SvT_h[idx] = g_skv_h[s];
        g_SvT_l[idx] = g_skv_l[s];
    } else if (j < LS) {
        wsplit(SQRT_M * Sm_v[h * (MTOK * DD) + (j - NN_) * DD + d], g_SvT_h, g_SvT_l, idx);
    } else {
        g_SvT_h[idx] = __float2bfloat16(0.f);
        g_SvT_l[idx] = __float2bfloat16(0.f);
    }
}

// WfT[k, o] = Wf[o, k], split bf16, zero-padded to [LKP, LSP]
__global__ void transpose_WfT(const float* __restrict__ Wf)
{
    long idx = (long)blockIdx.x * blockDim.x + threadIdx.x;
    const long total = (long)LKP * LSP;
    if (idx >= total) return;
    long k = idx / LSP, o = idx - k * LSP;
    float v = (k < LK && o < LS) ? Wf[o * (long)LK + k] : 0.0f;
    wsplit(v, g_WfT_h, g_WfT_l, idx);
}

// cvec[z, d] = sum_o bf[o] * Sv[z, o, d]  (one warp per (z,d))
__global__ void calc_cvec(const float* __restrict__ bf)
{
    int w = (blockIdx.x * blockDim.x + threadIdx.x) >> 5;
    int lane = threadIdx.x & 31;
    if (w >= ZZ * DD) return;
    const bf16* sh_ = g_SvT_h + (long)w * LSP;
    const bf16* sl_ = g_SvT_l + (long)w * LSP;
    float s = 0.0f;
    for (int o = lane; o < LS; o += 32)
        s += bf[o] * (__bfloat162float(sh_[o]) + __bfloat162float(sl_[o]));
    #pragma unroll
    for (int sft = 16; sft > 0; sft >>= 1)
        s += __shfl_xor_sync(0xFFFFFFFF, s, sft);
    if (lane == 0) g_cvec[w] = s;
}

// ---------------- launch ----------------
static inline dim3 eltGrid(long n) { return dim3((unsigned)((n + 255) / 256)); }
static inline unsigned cdiv(int a, int b) { return (unsigned)((a + b - 1) / b); }

#define GETP(T, v, sym) T* v; cudaGetSymbolAddress((void**)&v, sym)

// dynamic smem sizes (3 stages x R x 40 elems x 2B); also >= exp staging (2x64xEPLD)
#define SMEM_128_128 (3 * 256 * 40 * 2)
#define SMEM_64_128  (3 * 192 * 40 * 2)
#define SMEM_128_64  (3 * 192 * 40 * 2)

extern "C" void kernel_launch(void* const* d_in, const int* in_sizes, int n_in,
                              void* d_out, int out_size)
{
    const float* inp  = (const float*)d_in[0];
    const float* x    = (const float*)d_in[1];
    const float* y    = (const float*)d_in[2];
    const float* Wq   = (const float*)d_in[3];
    const float* bq   = (const float*)d_in[4];
    const float* Wkv  = (const float*)d_in[5];
    const float* bkv  = (const float*)d_in[6];
    const float* Wf   = (const float*)d_in[7];
    const float* bf   = (const float*)d_in[8];
    const float* Wo   = (const float*)d_in[9];
    const float* bo   = (const float*)d_in[10];
    const float* m_k  = (const float*)d_in[11];
    // d_in[12] = m_v : unused (cross-attention v never feeds the output)
    const float* Sm_k = (const float*)d_in[13];
    const float* Sm_v = (const float*)d_in[14];
    float* out = (float*)d_out;

    GETP(bf16, p_inp_h, g_inp_h);   GETP(bf16, p_inp_l, g_inp_l);
    GETP(bf16, p_ctx_h, g_ctx_h);   GETP(bf16, p_ctx_l, g_ctx_l);
    GETP(bf16, p_Wq_h,  g_Wq_h);    GETP(bf16, p_Wq_l,  g_Wq_l);
    GETP(bf16, p_Wkv_h, g_Wkv_h);   GETP(bf16, p_Wkv_l, g_Wkv_l);
    GETP(bf16, p_Wo_h,  g_Wo_h);    GETP(bf16, p_Wo_l,  g_Wo_l);
    GETP(bf16, p_qlin_h,g_qlin_h);  GETP(bf16, p_qlin_l,g_qlin_l);
    GETP(bf16, p_kctx_h,g_kctx_h);  GETP(bf16, p_kctx_l,g_kctx_l);
    GETP(bf16, p_skv_h, g_skv_h);   GETP(bf16, p_skv_l, g_skv_l);
    GETP(bf16, p_Q_h,   g_Q_h);     GETP(bf16, p_Q_l,   g_Q_l);
    GETP(bf16, p_K_h,   g_K_h);     GETP(bf16, p_K_l,   g_K_l);
    GETP(bf16, p_Sk_h,  g_Sk_h);    GETP(bf16, p_Sk_l,  g_Sk_l);
    GETP(bf16, p_SvT_h, g_SvT_h);   GETP(bf16, p_SvT_l, g_SvT_l);
    GETP(bf16, p_WfT_h, g_WfT_h);   GETP(bf16, p_WfT_l, g_WfT_l);
    GETP(bf16, p_Ph,    g_Ph);      GETP(bf16, p_Pl,    g_Pl);
    GETP(bf16, p_S2h,   g_S2h);     GETP(bf16, p_S2l,   g_S2l);
    GETP(bf16, p_Gt_h,  g_Gt_h);    GETP(bf16, p_Gt_l,  g_Gt_l);
    GETP(bf16, p_outp_h,g_outp_h);  GETP(bf16, p_outp_l,g_outp_l);
    GETP(float, p_rsumP, g_rsumP);
    GETP(float, p_rsumS, g_rsumS);
    GETP(float, p_cvec, g_cvec);
    GETP(float, p_obh,  g_obh);

    cudaFuncSetAttribute((const void*)gemm_bf<128,128>,
                         cudaFuncAttributeMaxDynamicSharedMemorySize, SMEM_128_128);
    cudaFuncSetAttribute((const void*)gemm_bf<64,128>,
                         cudaFuncAttributeMaxDynamicSharedMemorySize, SMEM_64_128);
    cudaFuncSetAttribute((const void*)gemm_bf<128,64>,
                         cudaFuncAttributeMaxDynamicSharedMemorySize, SMEM_128_64);

    // 0. zero row-sum accumulators (graph-capturable async memset)
    cudaMemsetAsync(p_rsumP, 0, (size_t)ZZ * NN_ * sizeof(float));
    cudaMemsetAsync(p_rsumS, 0, (size_t)ZZ * NN_ * sizeof(float));

    // 1. fused input splits + context pack (ONE launch)
    const long n_split = (long)BB * NN_ * DIM_ + (long)INNER_ * DIM_
                       + (long)2 * INNER_ * DIM_ + (long)DIM_ * INNER_
                       + (long)CTX * BB * DIM_;
    split_all<<<eltGrid(n_split), 256>>>(inp, Wq, Wkv, Wo, x, y);

    // 2. q_lin = inp @ Wq^T + bq   [8192, 512] K=512 -> split bf16
    gemm_bf<128,128><<<dim3(cdiv(INNER_,128), cdiv(BB*NN_,128), 1), 256, SMEM_128_128>>>(
        p_inp_h, p_inp_l, DIM_, 0, p_Wq_h, p_Wq_l, DIM_, 0,
        bq, nullptr, 0, nullptr, 0, 0,
        nullptr, p_qlin_h, p_qlin_l, INNER_, 0, BB*NN_, INNER_, DIM_, 1.0f,
        nullptr, 0, 0, nullptr, 0, 0);

    // 3. k_ctx = context @ Wkv[0:512]^T + bkv[0:512]   [16384, 512] (v half dead)
    gemm_bf<128,128><<<dim3(cdiv(INNER_,128), cdiv(BB*CTX,128), 1), 256, SMEM_128_128>>>(
        p_ctx_h, p_ctx_l, DIM_, 0, p_Wkv_h, p_Wkv_l, DIM_, 0,
        bkv, nullptr, 0, nullptr, 0, 0,
        nullptr, p_kctx_h, p_kctx_l, INNER_, 0, BB*CTX, INNER_, DIM_, 1.0f,
        nullptr, 0, 0, nullptr, 0, 0);

    // 4. skv = inp @ Wkv^T + bkv   [8192, 1024]
    gemm_bf<128,128><<<dim3(cdiv(2*INNER_,128), cdiv(BB*NN_,128), 1), 256, SMEM_128_128>>>(
        p_inp_h, p_inp_l, DIM_, 0, p_Wkv_h, p_Wkv_l, DIM_, 0,
        bkv, nullptr, 0, nullptr, 0, 0,
        nullptr, p_skv_h, p_skv_l, 2*INNER_, 0, BB*NN_, 2*INNER_, DIM_, 1.0f,
        nullptr, 0, 0, nullptr, 0, 0);

    // 5. packs (+ memory tokens, + zero pads), WfT, cvec
    pack_Q_split  <<<eltGrid((long)ZZ * NN_ * DD), 256>>>();
    pack_K_split  <<<eltGrid((long)ZZ * LKP * DD), 256>>>(m_k);
    pack_Sk_split <<<eltGrid((long)ZZ * LSP * DD), 256>>>(Sm_k);
    pack_SvT_split<<<eltGrid((long)ZZ * DD * LSP), 256>>>(Sm_v);
    transpose_WfT <<<eltGrid((long)LKP * LSP), 256>>>(Wf);
    calc_cvec     <<<cdiv(ZZ * DD * 32, 256), 256>>>(bf);

    // 6. cross scores -> EXP MODE: Ph/Pl = exp(SCALE * Q @ K^T), rsumP += rows
    //    [64 x 1024 x 2051] K=64; pads [LK, LKP) zero-filled; staged stores
    gemm_bf<128,128><<<dim3(cdiv(LKP,128), cdiv(NN_,128), ZZ), 256, SMEM_128_128>>>(
        p_Q_h, p_Q_l, DD, (long)NN_*DD, p_K_h, p_K_l, DD, (long)LKP*DD,
        nullptr, nullptr, 0, nullptr, 0, 0,
        nullptr, p_Ph, p_Pl, LKP, (long)NN_*LKP, NN_, LK, DD, SCALE_,
        p_rsumP, NN_, LKP, nullptr, 0, 0);

    //    self scores -> EXP MODE: S2h/S2l = exp(SCALE * Q @ Sk^T), rsumS
    gemm_bf<128,128><<<dim3(cdiv(LSP,128), cdiv(NN_,128), ZZ), 256, SMEM_128_128>>>(
        p_Q_h, p_Q_l, DD, (long)NN_*DD, p_Sk_h, p_Sk_l, DD, (long)LSP*DD,
        nullptr, nullptr, 0, nullptr, 0, 0,
        nullptr, p_S2h, p_S2l, LSP, (long)NN_*LSP, NN_, LS, DD, SCALE_,
        p_rsumS, NN_, LSP, nullptr, 0, 0);

    // 7a. Gt[z][d,k] = sum_o Sv[o,d] Wf[o,k]  [64 x (64 x 2064), K=1040] -> split
    gemm_bf<64,128><<<dim3(cdiv(LKP,128), 1, ZZ), 256, SMEM_64_128>>>(
        p_SvT_h, p_SvT_l, LSP, (long)DD*LSP, p_WfT_h, p_WfT_l, LSP, 0,
        nullptr, nullptr, 0, nullptr, 0, 0,
        nullptr, p_Gt_h, p_Gt_l, LKP, (long)DD*LKP, DD, LKP, LSP, 1.0f,
        nullptr, 0, 0, nullptr, 0, 0);

    // 7b. obh = (expS2 @ Sv) / rsumS   [64 x 1024 x 64, K=1040] -> fp32
    gemm_bf<128,64><<<dim3(1, cdiv(NN_,128), ZZ), 256, SMEM_128_64>>>(
        p_S2h, p_S2l, LSP, (long)NN_*LSP, p_SvT_h, p_SvT_l, LSP, (long)DD*LSP,
        nullptr, nullptr, 0, nullptr, 0, 0,
        p_obh, nullptr, nullptr, DD, (long)NN_*DD, NN_, DD, LSP, 1.0f,
        nullptr, 0, 0, p_rsumS, NN_, 0);

    // 7c. outp = (expP @ Gt^T)/rsumP + cvec + obh -> split bf16, HEAD-MERGED
    //     [64 x 1024 x 64, K=2064]
    gemm_bf<128,64><<<dim3(1, cdiv(NN_,128), ZZ), 256, SMEM_128_64>>>(
        p_Ph, p_Pl, LKP, (long)NN_*LKP, p_Gt_h, p_Gt_l, LKP, (long)DD*LKP,
        nullptr, p_cvec, DD, p_obh, DD, (long)NN_*DD,
        nullptr, p_outp_h, p_outp_l, INNER_, 0, NN_, DD, LKP, 1.0f,
        nullptr, 0, 0, p_rsumP, NN_, 1);

    // 8. final = outp @ Wo^T + bo   [8192, 512] K=512 -> fp32 d_out
    gemm_bf<128,128><<<dim3(cdiv(DIM_,128), cdiv(BB*NN_,128), 1), 256, SMEM_128_128>>>(
        p_outp_h, p_outp_l, INNER_, 0, p_Wo_h, p_Wo_l, INNER_, 0,
        bo, nullptr, 0, nullptr, 0, 0,
        out, nullptr, nullptr, DIM_, 0, BB*NN_, DIM_, INNER_, 1.0f,
        nullptr, 0, 0, nullptr, 0, 0);
}